// round 1
// baseline (speedup 1.0000x reference)
#include <cuda_runtime.h>
#include <math.h>

#define BB    4
#define CC    512
#define NSEQ  2048
#define GG    8
#define DD    64          // CG = headdim
#define BM    128
#define BN    128
#define VS    68          // padded Vst row stride (16B-aligned rows: 68*4=272=17*16)

// Scratch: conv output t, laid out [b, g, cg, n] == [B, C, N] flat (16 MB)
__device__ float g_t[(size_t)BB * CC * NSEQ];
// GroupNorm stats per (b, j): mean, rstd
__device__ float g_stats[BB * GG * 2];

// ---------------------------------------------------------------------------
// Kernel A: grouped 1x1 conv.  t[b,g,o,n] = sum_i W[g,o,i]*x[b,g,i,n] + bias
// grid (B*G, N/64), block 256
// ---------------------------------------------------------------------------
__global__ __launch_bounds__(256)
void conv_kernel(const float* __restrict__ points,
                 const float* __restrict__ cw,
                 const float* __restrict__ cb) {
    __shared__ float WsT[64 * 64];   // [i][o]  (transposed for contiguous o reads)
    __shared__ float xs[64 * 64];    // [i][n]
    const int head = blockIdx.x;       // b*G + g
    const int g    = head & 7;
    const int n0   = blockIdx.y * 64;
    const int tid  = threadIdx.x;

    for (int idx = tid; idx < 64 * 64; idx += 256) {
        int o = idx >> 6, i = idx & 63;
        WsT[i * 64 + o] = cw[(g * 64 + o) * 64 + i];
    }
    const float* xb = points + (size_t)head * 64 * NSEQ + n0;
    for (int idx = tid; idx < 64 * 64; idx += 256) {
        int i = idx >> 6, n = idx & 63;
        xs[i * 64 + n] = xb[i * NSEQ + n];
    }
    __syncthreads();

    const int o0 = (tid >> 5) * 8;   // warp -> 8 output channels (broadcast W reads)
    const int nn = (tid & 31) * 2;   // lane -> 2 columns
    float acc0[8], acc1[8];
#pragma unroll
    for (int u = 0; u < 8; u++) { acc0[u] = 0.f; acc1[u] = 0.f; }

    for (int i = 0; i < 64; i++) {
        float x0 = xs[i * 64 + nn];
        float x1 = xs[i * 64 + nn + 1];
#pragma unroll
        for (int u = 0; u < 8; u++) {
            float w = WsT[i * 64 + o0 + u];
            acc0[u] += w * x0;
            acc1[u] += w * x1;
        }
    }
    float* tb = g_t + (size_t)head * 64 * NSEQ + n0;
#pragma unroll
    for (int u = 0; u < 8; u++) {
        float bias = cb[g * 64 + o0 + u];
        float2 r = make_float2(acc0[u] + bias, acc1[u] + bias);
        *(float2*)&tb[(o0 + u) * NSEQ + nn] = r;
    }
}

// ---------------------------------------------------------------------------
// Kernel B: flash attention per head with Q=K=t, V=elu(t).
// Softmax over axis=-2 of S[n,m] == softmax over keys n for query m
// (S is symmetric), so this is standard flash attention.
// Fuses channel shuffle (c' = cg*8+g) + residual into the epilogue.
// grid (N/BM, B*G), block 256, dynamic smem 165888 B
// ---------------------------------------------------------------------------
__global__ __launch_bounds__(256, 1)
void attn_kernel(const float* __restrict__ points, float* __restrict__ out) {
    extern __shared__ float sm[];
    float* Qs  = sm;                    // [64][BM]   (scaled by 1/8)
    float* Ks  = Qs  + 64 * BM;         // [64][BN]
    float* Pst = Ks  + 64 * BN;         // [BM][BN]   P, i-major
    float* Vst = Pst + BM * BN;         // [BN][VS]   elu(K) transposed

    const int tid  = threadIdx.x;
    const int ty   = tid >> 4;          // 0..15 -> query sub-rows
    const int tx   = tid & 15;          // 0..15 -> key sub-cols / out channels
    const int head = blockIdx.y;
    const int b    = head >> 3;
    const int g    = head & 7;
    const int m0   = blockIdx.x * BM;
    const float* tbase = g_t + (size_t)head * DD * NSEQ;

    const int i0 = ty * 8;              // my 8 query rows
    const int j0 = tx * 8;              // my 8 key cols (GEMM1)
    const int c0 = tx * 4;              // my 4 out channels (GEMM2)

    // load Q tile, scale folded in (scale = 1/sqrt(64) = 0.125)
    for (int idx = tid; idx < DD * BM; idx += 256) {
        int c = idx >> 7, i = idx & 127;
        Qs[c * BM + i] = tbase[c * NSEQ + m0 + i] * 0.125f;
    }

    float m_run[8], l_run[8], Oacc[8][4];
#pragma unroll
    for (int u = 0; u < 8; u++) {
        m_run[u] = -1e30f; l_run[u] = 0.f;
#pragma unroll
        for (int w = 0; w < 4; w++) Oacc[u][w] = 0.f;
    }

    for (int kb = 0; kb < NSEQ / BN; kb++) {
        const int n0 = kb * BN;
        for (int idx = tid; idx < DD * BN; idx += 256) {
            int c = idx >> 7, j = idx & 127;
            Ks[c * BN + j] = tbase[c * NSEQ + n0 + j];
        }
        __syncthreads();   // Ks ready; also fences prior iter's GEMM2 reads

        // ---- GEMM1: S = Q^T K (8x8 register tile) ----
        float S[8][8];
#pragma unroll
        for (int u = 0; u < 8; u++)
#pragma unroll
            for (int v = 0; v < 8; v++) S[u][v] = 0.f;

        for (int c = 0; c < DD; c++) {
            float4 qa = *(const float4*)&Qs[c * BM + i0];
            float4 qb = *(const float4*)&Qs[c * BM + i0 + 4];
            float4 ka = *(const float4*)&Ks[c * BN + j0];
            float4 kb4 = *(const float4*)&Ks[c * BN + j0 + 4];
            float q[8] = {qa.x, qa.y, qa.z, qa.w, qb.x, qb.y, qb.z, qb.w};
            float k[8] = {ka.x, ka.y, ka.z, ka.w, kb4.x, kb4.y, kb4.z, kb4.w};
#pragma unroll
            for (int u = 0; u < 8; u++)
#pragma unroll
                for (int v = 0; v < 8; v++) S[u][v] += q[u] * k[v];
        }

        // ---- online softmax (rows shared by 16 tx lanes; shuffle-reduce) ----
#pragma unroll
        for (int u = 0; u < 8; u++) {
            float tmax = S[u][0];
#pragma unroll
            for (int v = 1; v < 8; v++) tmax = fmaxf(tmax, S[u][v]);
#pragma unroll
            for (int off = 8; off; off >>= 1)
                tmax = fmaxf(tmax, __shfl_xor_sync(0xffffffffu, tmax, off));
            float mn = fmaxf(m_run[u], tmax);
            float corr = __expf(m_run[u] - mn);
            m_run[u] = mn;
            float rs = 0.f;
#pragma unroll
            for (int v = 0; v < 8; v++) {
                float p = __expf(S[u][v] - mn);
                Pst[(i0 + u) * BN + j0 + v] = p;
                rs += p;
            }
#pragma unroll
            for (int off = 8; off; off >>= 1)
                rs += __shfl_xor_sync(0xffffffffu, rs, off);
            l_run[u] = l_run[u] * corr + rs;
#pragma unroll
            for (int w = 0; w < 4; w++) Oacc[u][w] *= corr;
        }

        // ---- V = elu(K), transposed into [j][c] ----
        for (int idx = tid; idx < DD * BN; idx += 256) {
            int c = idx >> 7, j = idx & 127;
            float x = Ks[c * BN + j];
            Vst[j * VS + c] = (x > 0.f) ? x : (__expf(x) - 1.f);
        }
        __syncthreads();   // Pst + Vst complete

        // ---- GEMM2: O += P @ V  (8 rows x 4 channels per thread) ----
        for (int j = 0; j < BN; j += 4) {
            float4 p4[8];
#pragma unroll
            for (int u = 0; u < 8; u++)
                p4[u] = *(const float4*)&Pst[(i0 + u) * BN + j];
            float4 v4[4];
#pragma unroll
            for (int t = 0; t < 4; t++)
                v4[t] = *(const float4*)&Vst[(j + t) * VS + c0];
#pragma unroll
            for (int t = 0; t < 4; t++) {
                float vx = v4[t].x, vy = v4[t].y, vz = v4[t].z, vw = v4[t].w;
#pragma unroll
                for (int u = 0; u < 8; u++) {
                    float p = ((const float*)&p4[u])[t];
                    Oacc[u][0] += p * vx;
                    Oacc[u][1] += p * vy;
                    Oacc[u][2] += p * vz;
                    Oacc[u][3] += p * vw;
                }
            }
        }
        // no trailing sync needed: next iter only writes Ks (dead after elu),
        // and its Pst/Vst writes sit behind next iter's first __syncthreads.
    }

    // ---- epilogue: normalize, channel shuffle (c' = cg*8+g), residual ----
#pragma unroll
    for (int u = 0; u < 8; u++) {
        float inv = 1.f / l_run[u];
        int m = m0 + i0 + u;
#pragma unroll
        for (int w = 0; w < 4; w++) {
            int cp = (c0 + w) * GG + g;
            size_t oidx = ((size_t)(b * CC + cp)) * NSEQ + m;
            out[oidx] = Oacc[u][w] * inv + points[oidx];
        }
    }
}

// ---------------------------------------------------------------------------
// Kernel C1: GroupNorm stats. After shuffle, GN group (b,j) covers channels
// [64j, 64j+64) which is a CONTIGUOUS 64*2048-float slab of out.
// grid 32, block 512
// ---------------------------------------------------------------------------
__global__ __launch_bounds__(512)
void gn_stats(const float* __restrict__ out) {
    __shared__ float ssum[16], ssq[16];
    const int bj = blockIdx.x;
    const float4* base = (const float4*)(out + (size_t)bj * 64 * NSEQ);
    const int n4 = 64 * NSEQ / 4;
    float s = 0.f, q = 0.f;
    for (int i = threadIdx.x; i < n4; i += blockDim.x) {
        float4 v = base[i];
        s += v.x + v.y + v.z + v.w;
        q += v.x * v.x + v.y * v.y + v.z * v.z + v.w * v.w;
    }
#pragma unroll
    for (int off = 16; off; off >>= 1) {
        s += __shfl_xor_sync(0xffffffffu, s, off);
        q += __shfl_xor_sync(0xffffffffu, q, off);
    }
    int warp = threadIdx.x >> 5, lane = threadIdx.x & 31;
    if (lane == 0) { ssum[warp] = s; ssq[warp] = q; }
    __syncthreads();
    if (warp == 0) {
        s = (lane < 16) ? ssum[lane] : 0.f;
        q = (lane < 16) ? ssq[lane] : 0.f;
#pragma unroll
        for (int off = 8; off; off >>= 1) {
            s += __shfl_xor_sync(0xffffffffu, s, off);
            q += __shfl_xor_sync(0xffffffffu, q, off);
        }
        if (lane == 0) {
            const float invN = 1.f / (64.f * NSEQ);
            float mean = s * invN;
            float var = q * invN - mean * mean;
            g_stats[bj * 2]     = mean;
            g_stats[bj * 2 + 1] = rsqrtf(var + 1e-5f);
        }
    }
}

// ---------------------------------------------------------------------------
// Kernel C2: normalize in place + affine. grid 4096, block 256 (float4)
// ---------------------------------------------------------------------------
__global__ __launch_bounds__(256)
void gn_norm(float* __restrict__ out,
             const float* __restrict__ gw, const float* __restrict__ gb) {
    const int TOT4 = BB * CC * NSEQ / 4;
    int i4 = blockIdx.x * blockDim.x + threadIdx.x;
    if (i4 >= TOT4) return;
    int row = i4 >> 9;            // NSEQ/4 = 512 float4 per channel-row
    int cp  = row & 511;
    int b   = row >> 9;
    int bj  = (b << 3) | (cp >> 6);
    float mean = g_stats[bj * 2];
    float rstd = g_stats[bj * 2 + 1];
    float ws = gw[cp] * rstd;
    float sh = gb[cp] - mean * ws;
    float4 v = ((float4*)out)[i4];
    v.x = v.x * ws + sh;
    v.y = v.y * ws + sh;
    v.z = v.z * ws + sh;
    v.w = v.w * ws + sh;
    ((float4*)out)[i4] = v;
}

// ---------------------------------------------------------------------------
extern "C" void kernel_launch(void* const* d_in, const int* in_sizes, int n_in,
                              void* d_out, int out_size) {
    const float* points = (const float*)d_in[0];
    const float* conv_w = (const float*)d_in[1];
    const float* conv_b = (const float*)d_in[2];
    const float* gn_w   = (const float*)d_in[3];
    const float* gn_b   = (const float*)d_in[4];
    float* out = (float*)d_out;

    const int ATTN_SMEM = (64 * BM + 64 * BN + BM * BN + BN * VS) * 4; // 165888
    cudaFuncSetAttribute(attn_kernel,
                         cudaFuncAttributeMaxDynamicSharedMemorySize, ATTN_SMEM);

    conv_kernel<<<dim3(BB * GG, NSEQ / 64), 256>>>(points, conv_w, conv_b);
    attn_kernel<<<dim3(NSEQ / BM, BB * GG), 256, ATTN_SMEM>>>(points, out);
    gn_stats<<<BB * GG, 512>>>(out);
    gn_norm<<<(BB * CC * NSEQ / 4 + 255) / 256, 256>>>(out, gn_w, gn_b);
}

// round 4
// speedup vs baseline: 3.7365x; 3.7365x over previous
#include <cuda_runtime.h>
#include <cuda_bf16.h>
#include <math.h>
#include <stdint.h>

#define BB    4
#define CC    512
#define NSEQ  2048
#define GG    8
#define DD    64
#define HEADS 32
#define BM    128
#define BN    64

// bf16 split of sqrt(1/8)*t, key-major [head][n][c]
__device__ __nv_bfloat16 g_th[(size_t)HEADS * NSEQ * DD];
__device__ __nv_bfloat16 g_tl[(size_t)HEADS * NSEQ * DD];
// bf16 elu(t), channel-major [head][c][n]
__device__ __nv_bfloat16 g_v[(size_t)HEADS * DD * NSEQ];
__device__ float g_stats[BB * GG * 2];

// ============================ PTX helpers ==================================
__device__ __forceinline__ uint32_t smem_u32(const void* p) {
    uint32_t a;
    asm("{ .reg .u64 t; cvta.to.shared.u64 t, %1; cvt.u32.u64 %0, t; }" : "=r"(a) : "l"(p));
    return a;
}
__device__ __forceinline__ void ldsm4(uint32_t& r0, uint32_t& r1, uint32_t& r2,
                                      uint32_t& r3, uint32_t addr) {
    asm volatile("ldmatrix.sync.aligned.m8n8.x4.shared.b16 {%0,%1,%2,%3}, [%4];"
                 : "=r"(r0), "=r"(r1), "=r"(r2), "=r"(r3) : "r"(addr));
}
__device__ __forceinline__ void mma16816(float* c, uint32_t a0, uint32_t a1,
                                         uint32_t a2, uint32_t a3,
                                         uint32_t b0, uint32_t b1) {
    asm volatile("mma.sync.aligned.m16n8k16.row.col.f32.bf16.bf16.f32 "
                 "{%0,%1,%2,%3}, {%4,%5,%6,%7}, {%8,%9}, {%0,%1,%2,%3};"
                 : "+f"(c[0]), "+f"(c[1]), "+f"(c[2]), "+f"(c[3])
                 : "r"(a0), "r"(a1), "r"(a2), "r"(a3), "r"(b0), "r"(b1));
}
__device__ __forceinline__ uint32_t pack_bf2(float lo, float hi) {
    uint32_t r;
    asm("cvt.rn.bf16x2.f32 %0, %1, %2;" : "=r"(r) : "f"(hi), "f"(lo));
    return r;
}

// ---------------------------------------------------------------------------
// Kernel A: grouped 1x1 conv -> bf16 splits (q/k, [n][c]) + bf16 elu (v, [c][n])
// grid (32 heads, 32 n-blocks), block 256
// ---------------------------------------------------------------------------
__global__ __launch_bounds__(256)
void conv_kernel(const float* __restrict__ points,
                 const float* __restrict__ cw,
                 const float* __restrict__ cb) {
    __shared__ float WsT[64 * 64];   // [i][o]
    __shared__ float xs[64 * 64];    // [i][n] -> reused as t [n][c]
    const int head = blockIdx.x;
    const int g    = head & 7;
    const int n0   = blockIdx.y * 64;
    const int tid  = threadIdx.x;

    for (int idx = tid; idx < 4096; idx += 256) {
        int o = idx >> 6, i = idx & 63;
        WsT[i * 64 + o] = cw[(g * 64 + o) * 64 + i];
    }
    const float* xb = points + (size_t)head * DD * NSEQ + n0;
    for (int idx = tid; idx < 4096; idx += 256) {
        int i = idx >> 6, n = idx & 63;
        xs[i * 64 + n] = xb[(size_t)i * NSEQ + n];
    }
    __syncthreads();

    const int o0 = (tid >> 5) * 8;
    const int nn = (tid & 31) * 2;
    float acc0[8], acc1[8];
#pragma unroll
    for (int u = 0; u < 8; u++) { acc0[u] = 0.f; acc1[u] = 0.f; }
    for (int i = 0; i < 64; i++) {
        float x0 = xs[i * 64 + nn];
        float x1 = xs[i * 64 + nn + 1];
#pragma unroll
        for (int u = 0; u < 8; u++) {
            float w = WsT[i * 64 + o0 + u];
            acc0[u] += w * x0;
            acc1[u] += w * x1;
        }
    }
    float v0r[8], v1r[8];
#pragma unroll
    for (int u = 0; u < 8; u++) {
        float bias = cb[g * 64 + o0 + u];
        v0r[u] = acc0[u] + bias;
        v1r[u] = acc1[u] + bias;
    }
    __nv_bfloat16* vb = g_v + (size_t)head * DD * NSEQ + n0 + nn;
#pragma unroll
    for (int u = 0; u < 8; u++) {
        float e0 = (v0r[u] > 0.f) ? v0r[u] : (__expf(v0r[u]) - 1.f);
        float e1 = (v1r[u] > 0.f) ? v1r[u] : (__expf(v1r[u]) - 1.f);
        __nv_bfloat162 p;
        p.x = __float2bfloat16(e0);
        p.y = __float2bfloat16(e1);
        *(__nv_bfloat162*)(vb + (size_t)(o0 + u) * NSEQ) = p;
    }
    __syncthreads();
#pragma unroll
    for (int u = 0; u < 8; u++) {
        xs[nn * 64 + o0 + u]       = v0r[u];
        xs[(nn + 1) * 64 + o0 + u] = v1r[u];
    }
    __syncthreads();
    __nv_bfloat16* thb = g_th + ((size_t)head * NSEQ + n0) * DD;
    __nv_bfloat16* tlb = g_tl + ((size_t)head * NSEQ + n0) * DD;
    const float SC = 0.35355339059327376f;   // sqrt(0.125)
    for (int idx = tid; idx < 2048; idx += 256) {
        int n = idx >> 5, c2 = (idx & 31) * 2;
        float x0 = xs[n * 64 + c2] * SC;
        float x1 = xs[n * 64 + c2 + 1] * SC;
        __nv_bfloat16 h0 = __float2bfloat16(x0);
        __nv_bfloat16 h1 = __float2bfloat16(x1);
        __nv_bfloat162 hh; hh.x = h0; hh.y = h1;
        __nv_bfloat162 ll;
        ll.x = __float2bfloat16(x0 - __bfloat162float(h0));
        ll.y = __float2bfloat16(x1 - __bfloat162float(h1));
        *(__nv_bfloat162*)(thb + n * 64 + c2) = hh;
        *(__nv_bfloat162*)(tlb + n * 64 + c2) = ll;
    }
}

// ---------------------------------------------------------------------------
// Kernel B: mma.sync flash attention. grid (16 m-blocks, 32 heads), block 128.
// Dynamic smem (57344 B): QH | QL | KH | KL | V  (uint4-sized tiles, swizzled)
// ---------------------------------------------------------------------------
#define ATTN_SMEM ((BM * 8 * 2 + BN * 8 * 2 + DD * 8) * 16)   // 57344

__global__ __launch_bounds__(128, 2)
void attn_kernel(const float* __restrict__ points, float* __restrict__ out) {
    extern __shared__ __align__(128) uint4 dynsm[];
    uint4* sQH = dynsm;                 // [BM*8]  16 KB
    uint4* sQL = sQH + BM * 8;          // 16 KB
    uint4* sKH = sQL + BM * 8;          // [BN*8]  8 KB
    uint4* sKL = sKH + BN * 8;          // 8 KB
    uint4* sV  = sKL + BN * 8;          // [DD*8]  8 KB

    const int tid  = threadIdx.x;
    const int wid  = tid >> 5;
    const int lane = tid & 31;
    const int grp  = lane >> 2;      // 0..7  (fragment row group)
    const int tq   = lane & 3;       // 0..3
    const int head = blockIdx.y;
    const int b    = head >> 3;
    const int hg   = head & 7;
    const int m0   = blockIdx.x * BM;
    const int wrow = wid * 32;

    const __nv_bfloat16* thB = g_th + (size_t)head * NSEQ * DD;
    const __nv_bfloat16* tlB = g_tl + (size_t)head * NSEQ * DD;
    const __nv_bfloat16* vB  = g_v  + (size_t)head * DD * NSEQ;

    const uint32_t bQH = smem_u32(sQH);
    const uint32_t bQL = smem_u32(sQL);
    const uint32_t bKH = smem_u32(sKH);
    const uint32_t bKL = smem_u32(sKL);
    const uint32_t bV  = smem_u32(sV);

    // ---- load Q tiles (swizzled: chunk' = chunk ^ (row&7)) ----
    {
        const uint4* s1 = (const uint4*)(thB + (size_t)m0 * DD);
        const uint4* s2 = (const uint4*)(tlB + (size_t)m0 * DD);
        for (int idx = tid; idx < BM * 8; idx += 128) {
            int r = idx >> 3, ch = idx & 7;
            int d = r * 8 + (ch ^ (r & 7));
            sQH[d] = s1[idx];
            sQL[d] = s2[idx];
        }
    }
    __syncthreads();

    // ---- persistent Qh fragments: [mtile][kstep][4] ----
    uint32_t qhf[2][4][4];
#pragma unroll
    for (int mt = 0; mt < 2; mt++)
#pragma unroll
        for (int k = 0; k < 4; k++) {
            int row = wrow + mt * 16 + ((lane >> 3) & 1) * 8 + (lane & 7);
            int ch  = 2 * k + (lane >> 4);
            uint32_t addr = bQH + (uint32_t)((row * 8 + (ch ^ (row & 7))) * 16);
            ldsm4(qhf[mt][k][0], qhf[mt][k][1], qhf[mt][k][2], qhf[mt][k][3], addr);
        }

    float O[2][8][4];
    float lsum[2][2];
#pragma unroll
    for (int mt = 0; mt < 2; mt++) {
        lsum[mt][0] = 0.f; lsum[mt][1] = 0.f;
#pragma unroll
        for (int ct = 0; ct < 8; ct++)
#pragma unroll
            for (int r = 0; r < 4; r++) O[mt][ct][r] = 0.f;
    }

    // lane-pattern pieces for B-operand ldmatrix (K and V tiles)
    const int brow_off = ((lane >> 4) & 1) * 8 + (lane & 7);
    const int bch_off  = (lane >> 3) & 1;

    for (int kb = 0; kb < NSEQ / BN; kb++) {
        const int n0 = kb * BN;
        // ---- cooperative K/V tile loads ----
        {
            const uint4* s1 = (const uint4*)(thB + (size_t)n0 * DD);
            const uint4* s2 = (const uint4*)(tlB + (size_t)n0 * DD);
            for (int idx = tid; idx < BN * 8; idx += 128) {
                int r = idx >> 3, ch = idx & 7;
                int d = r * 8 + (ch ^ (r & 7));
                sKH[d] = s1[idx];
                sKL[d] = s2[idx];
            }
            for (int idx = tid; idx < DD * 8; idx += 128) {
                int c = idx >> 3, ch = idx & 7;
                sV[c * 8 + (ch ^ (c & 7))] =
                    *(const uint4*)(vB + (size_t)c * NSEQ + n0 + ch * 8);
            }
        }
        __syncthreads();

        // ---- GEMM1: S[2][8][4] ----
        float S[2][8][4];
#pragma unroll
        for (int mt = 0; mt < 2; mt++)
#pragma unroll
            for (int nt = 0; nt < 8; nt++)
#pragma unroll
                for (int r = 0; r < 4; r++) S[mt][nt][r] = 0.f;

#pragma unroll
        for (int k = 0; k < 4; k++) {
            uint32_t bh[8][2];
#pragma unroll
            for (int nt2 = 0; nt2 < 4; nt2++) {
                int row = nt2 * 16 + brow_off;
                int ch  = 2 * k + bch_off;
                uint32_t addr = bKH + (uint32_t)((row * 8 + (ch ^ (row & 7))) * 16);
                ldsm4(bh[2 * nt2][0], bh[2 * nt2][1], bh[2 * nt2 + 1][0],
                      bh[2 * nt2 + 1][1], addr);
            }
#pragma unroll
            for (int mt = 0; mt < 2; mt++)
#pragma unroll
                for (int nt = 0; nt < 8; nt++)
                    mma16816(S[mt][nt], qhf[mt][k][0], qhf[mt][k][1], qhf[mt][k][2],
                             qhf[mt][k][3], bh[nt][0], bh[nt][1]);
            // Ql fragments for this k-step
            uint32_t qlf[2][4];
#pragma unroll
            for (int mt = 0; mt < 2; mt++) {
                int row = wrow + mt * 16 + ((lane >> 3) & 1) * 8 + (lane & 7);
                int ch  = 2 * k + (lane >> 4);
                uint32_t addr = bQL + (uint32_t)((row * 8 + (ch ^ (row & 7))) * 16);
                ldsm4(qlf[mt][0], qlf[mt][1], qlf[mt][2], qlf[mt][3], addr);
            }
#pragma unroll
            for (int mt = 0; mt < 2; mt++)
#pragma unroll
                for (int nt = 0; nt < 8; nt++)
                    mma16816(S[mt][nt], qlf[mt][0], qlf[mt][1], qlf[mt][2],
                             qlf[mt][3], bh[nt][0], bh[nt][1]);
            // Kl B fragments (reuse bh)
#pragma unroll
            for (int nt2 = 0; nt2 < 4; nt2++) {
                int row = nt2 * 16 + brow_off;
                int ch  = 2 * k + bch_off;
                uint32_t addr = bKL + (uint32_t)((row * 8 + (ch ^ (row & 7))) * 16);
                ldsm4(bh[2 * nt2][0], bh[2 * nt2][1], bh[2 * nt2 + 1][0],
                      bh[2 * nt2 + 1][1], addr);
            }
#pragma unroll
            for (int mt = 0; mt < 2; mt++)
#pragma unroll
                for (int nt = 0; nt < 8; nt++)
                    mma16816(S[mt][nt], qhf[mt][k][0], qhf[mt][k][1], qhf[mt][k][2],
                             qhf[mt][k][3], bh[nt][0], bh[nt][1]);
        }

        // ---- exp + pack P (register-resident A fragments for GEMM2) ----
        uint32_t P[2][8][2];
#pragma unroll
        for (int mt = 0; mt < 2; mt++)
#pragma unroll
            for (int nt = 0; nt < 8; nt++) {
                float e0 = __expf(S[mt][nt][0]);
                float e1 = __expf(S[mt][nt][1]);
                float e2 = __expf(S[mt][nt][2]);
                float e3 = __expf(S[mt][nt][3]);
                lsum[mt][0] += e0 + e1;
                lsum[mt][1] += e2 + e3;
                P[mt][nt][0] = pack_bf2(e0, e1);
                P[mt][nt][1] = pack_bf2(e2, e3);
            }

        // ---- GEMM2: O += P * V ----
#pragma unroll
        for (int kn = 0; kn < 4; kn++) {
            uint32_t bv[8][2];
#pragma unroll
            for (int ct2 = 0; ct2 < 4; ct2++) {
                int row = ct2 * 16 + brow_off;
                int ch  = 2 * kn + bch_off;
                uint32_t addr = bV + (uint32_t)((row * 8 + (ch ^ (row & 7))) * 16);
                ldsm4(bv[2 * ct2][0], bv[2 * ct2][1], bv[2 * ct2 + 1][0],
                      bv[2 * ct2 + 1][1], addr);
            }
#pragma unroll
            for (int mt = 0; mt < 2; mt++)
#pragma unroll
                for (int ct = 0; ct < 8; ct++)
                    mma16816(O[mt][ct], P[mt][2 * kn][0], P[mt][2 * kn][1],
                             P[mt][2 * kn + 1][0], P[mt][2 * kn + 1][1],
                             bv[ct][0], bv[ct][1]);
        }
        __syncthreads();   // K/V smem reuse next iter
    }

    // ---- epilogue: row sums across quad lanes, normalize, shuffle, residual ----
#pragma unroll
    for (int mt = 0; mt < 2; mt++)
#pragma unroll
        for (int h = 0; h < 2; h++) {
            float v = lsum[mt][h];
            v += __shfl_xor_sync(0xffffffffu, v, 1);
            v += __shfl_xor_sync(0xffffffffu, v, 2);
            lsum[mt][h] = v;
        }

#pragma unroll
    for (int mt = 0; mt < 2; mt++) {
        const int row0 = m0 + wrow + mt * 16 + grp;
        const float inv0 = 1.f / lsum[mt][0];
        const float inv1 = 1.f / lsum[mt][1];
#pragma unroll
        for (int ct = 0; ct < 8; ct++) {
            int c0 = ct * 8 + 2 * tq;
            size_t i00 = ((size_t)(b * CC + c0 * GG + hg)) * NSEQ + row0;
            size_t i01 = ((size_t)(b * CC + (c0 + 1) * GG + hg)) * NSEQ + row0;
            out[i00]     = O[mt][ct][0] * inv0 + points[i00];
            out[i01]     = O[mt][ct][1] * inv0 + points[i01];
            out[i00 + 8] = O[mt][ct][2] * inv1 + points[i00 + 8];
            out[i01 + 8] = O[mt][ct][3] * inv1 + points[i01 + 8];
        }
    }
}

// ---------------------------------------------------------------------------
// GroupNorm
// ---------------------------------------------------------------------------
__global__ __launch_bounds__(512)
void gn_stats(const float* __restrict__ out) {
    __shared__ float ssum[16], ssq[16];
    const int bj = blockIdx.x;
    const float4* base = (const float4*)(out + (size_t)bj * 64 * NSEQ);
    const int n4 = 64 * NSEQ / 4;
    float s = 0.f, q = 0.f;
    for (int i = threadIdx.x; i < n4; i += blockDim.x) {
        float4 v = base[i];
        s += v.x + v.y + v.z + v.w;
        q += v.x * v.x + v.y * v.y + v.z * v.z + v.w * v.w;
    }
#pragma unroll
    for (int off = 16; off; off >>= 1) {
        s += __shfl_xor_sync(0xffffffffu, s, off);
        q += __shfl_xor_sync(0xffffffffu, q, off);
    }
    int warp = threadIdx.x >> 5, lane = threadIdx.x & 31;
    if (lane == 0) { ssum[warp] = s; ssq[warp] = q; }
    __syncthreads();
    if (warp == 0) {
        s = (lane < 16) ? ssum[lane] : 0.f;
        q = (lane < 16) ? ssq[lane] : 0.f;
#pragma unroll
        for (int off = 8; off; off >>= 1) {
            s += __shfl_xor_sync(0xffffffffu, s, off);
            q += __shfl_xor_sync(0xffffffffu, q, off);
        }
        if (lane == 0) {
            const float invN = 1.f / (64.f * NSEQ);
            float mean = s * invN;
            float var = q * invN - mean * mean;
            g_stats[bj * 2]     = mean;
            g_stats[bj * 2 + 1] = rsqrtf(var + 1e-5f);
        }
    }
}

__global__ __launch_bounds__(256)
void gn_norm(float* __restrict__ out,
             const float* __restrict__ gw, const float* __restrict__ gb) {
    const int TOT4 = BB * CC * NSEQ / 4;
    int i4 = blockIdx.x * blockDim.x + threadIdx.x;
    if (i4 >= TOT4) return;
    int row = i4 >> 9;
    int cp  = row & 511;
    int b   = row >> 9;
    int bj  = (b << 3) | (cp >> 6);
    float mean = g_stats[bj * 2];
    float rstd = g_stats[bj * 2 + 1];
    float ws = gw[cp] * rstd;
    float sh = gb[cp] - mean * ws;
    float4 v = ((float4*)out)[i4];
    v.x = v.x * ws + sh;
    v.y = v.y * ws + sh;
    v.z = v.z * ws + sh;
    v.w = v.w * ws + sh;
    ((float4*)out)[i4] = v;
}

// ---------------------------------------------------------------------------
extern "C" void kernel_launch(void* const* d_in, const int* in_sizes, int n_in,
                              void* d_out, int out_size) {
    const float* points = (const float*)d_in[0];
    const float* conv_w = (const float*)d_in[1];
    const float* conv_b = (const float*)d_in[2];
    const float* gn_w   = (const float*)d_in[3];
    const float* gn_b   = (const float*)d_in[4];
    float* out = (float*)d_out;

    cudaFuncSetAttribute(attn_kernel,
                         cudaFuncAttributeMaxDynamicSharedMemorySize, ATTN_SMEM);

    conv_kernel<<<dim3(HEADS, NSEQ / 64), 256>>>(points, conv_w, conv_b);
    attn_kernel<<<dim3(NSEQ / BM, HEADS), 128, ATTN_SMEM>>>(points, out);
    gn_stats<<<BB * GG, 512>>>(out);
    gn_norm<<<(BB * CC * NSEQ / 4 + 255) / 256, 256>>>(out, gn_w, gn_b);
}

// round 7
// speedup vs baseline: 7.2673x; 1.9449x over previous
#include <cuda_runtime.h>
#include <cuda_fp16.h>
#include <math.h>
#include <stdint.h>

#define BB    4
#define CC    512
#define NSEQ  2048
#define GG    8
#define DD    64
#define HEADS 32
#define BM    128
#define BN    64
#define NT    (NSEQ / BN)

// q/k = t * sqrt(0.125 * log2(e)), fp16, key-major [head][n][c]
__device__ __align__(16) __half g_th[(size_t)HEADS * NSEQ * DD];
// v = elu(t), fp16, channel-major [head][c][n]
__device__ __align__(16) __half g_v[(size_t)HEADS * DD * NSEQ];
// fused GN partials: per (b,j): {sum, sumsq}
__device__ float g_stats[BB * GG * 2];

#define QK_SCALE 0.4246609001440095f     // sqrt(0.125 * log2e)
#define EXP_SHIFT 11.541560327111707f    // 8 * log2e
#define P_CLAMP 32768.0f                 // keep P finite in fp16 (hot-row guard)

// ============================ PTX helpers ==================================
__device__ __forceinline__ uint32_t smem_u32(const void* p) {
    uint32_t a;
    asm("{ .reg .u64 t; cvta.to.shared.u64 t, %1; cvt.u32.u64 %0, t; }" : "=r"(a) : "l"(p));
    return a;
}
__device__ __forceinline__ void ldsm4(uint32_t& r0, uint32_t& r1, uint32_t& r2,
                                      uint32_t& r3, uint32_t addr) {
    asm volatile("ldmatrix.sync.aligned.m8n8.x4.shared.b16 {%0,%1,%2,%3}, [%4];"
                 : "=r"(r0), "=r"(r1), "=r"(r2), "=r"(r3) : "r"(addr));
}
__device__ __forceinline__ void mma16816(float* c, uint32_t a0, uint32_t a1,
                                         uint32_t a2, uint32_t a3,
                                         uint32_t b0, uint32_t b1) {
    asm volatile("mma.sync.aligned.m16n8k16.row.col.f32.f16.f16.f32 "
                 "{%0,%1,%2,%3}, {%4,%5,%6,%7}, {%8,%9}, {%0,%1,%2,%3};"
                 : "+f"(c[0]), "+f"(c[1]), "+f"(c[2]), "+f"(c[3])
                 : "r"(a0), "r"(a1), "r"(a2), "r"(a3), "r"(b0), "r"(b1));
}
__device__ __forceinline__ uint32_t pack_h2(float lo, float hi) {
    uint32_t r;
    asm("cvt.rn.f16x2.f32 %0, %1, %2;" : "=r"(r) : "f"(hi), "f"(lo));
    return r;
}
__device__ __forceinline__ void cpa16(uint32_t dst, const void* src) {
    asm volatile("cp.async.cg.shared.global [%0], [%1], 16;" :: "r"(dst), "l"(src));
}
#define CP_COMMIT() asm volatile("cp.async.commit_group;" ::: "memory")
#define CP_WAIT(n)  asm volatile("cp.async.wait_group %0;" :: "n"(n) : "memory")

// ---------------------------------------------------------------------------
// Kernel A: grouped 1x1 conv -> fp16 scaled t ([n][c]) + fp16 elu(t) ([c][n])
// grid (32 heads, 32 n-blocks), block 256
// ---------------------------------------------------------------------------
__global__ __launch_bounds__(256)
void conv_kernel(const float* __restrict__ points,
                 const float* __restrict__ cw,
                 const float* __restrict__ cb) {
    __shared__ float WsT[64 * 64];   // [i][o]
    __shared__ float xs[64 * 64];    // [i][n] -> reused as t [n][c]
    const int head = blockIdx.x;
    const int g    = head & 7;
    const int n0   = blockIdx.y * 64;
    const int tid  = threadIdx.x;

    if (head == 0 && blockIdx.y == 0 && tid < BB * GG * 2)
        g_stats[tid] = 0.f;          // reset fused-GN accumulators each launch

    for (int idx = tid; idx < 4096; idx += 256) {
        int o = idx >> 6, i = idx & 63;
        WsT[i * 64 + o] = cw[(g * 64 + o) * 64 + i];
    }
    const float* xb = points + (size_t)head * DD * NSEQ + n0;
    for (int idx = tid; idx < 4096; idx += 256) {
        int i = idx >> 6, n = idx & 63;
        xs[i * 64 + n] = xb[(size_t)i * NSEQ + n];
    }
    __syncthreads();

    const int o0 = (tid >> 5) * 8;
    const int nn = (tid & 31) * 2;
    float acc0[8], acc1[8];
#pragma unroll
    for (int u = 0; u < 8; u++) { acc0[u] = 0.f; acc1[u] = 0.f; }
    for (int i = 0; i < 64; i++) {
        float x0 = xs[i * 64 + nn];
        float x1 = xs[i * 64 + nn + 1];
#pragma unroll
        for (int u = 0; u < 8; u++) {
            float w = WsT[i * 64 + o0 + u];
            acc0[u] += w * x0;
            acc1[u] += w * x1;
        }
    }
    float v0r[8], v1r[8];
#pragma unroll
    for (int u = 0; u < 8; u++) {
        float bias = cb[g * 64 + o0 + u];
        v0r[u] = acc0[u] + bias;
        v1r[u] = acc1[u] + bias;
    }
    // V = elu(t), [c][n]-major (coalesced in n)
    __half* vb = g_v + (size_t)head * DD * NSEQ + n0 + nn;
#pragma unroll
    for (int u = 0; u < 8; u++) {
        float e0 = (v0r[u] > 0.f) ? v0r[u] : (__expf(v0r[u]) - 1.f);
        float e1 = (v1r[u] > 0.f) ? v1r[u] : (__expf(v1r[u]) - 1.f);
        __half2 p;
        p.x = __float2half_rn(e0);
        p.y = __float2half_rn(e1);
        *(__half2*)(vb + (size_t)(o0 + u) * NSEQ) = p;
    }
    __syncthreads();          // xs reads done
#pragma unroll
    for (int u = 0; u < 8; u++) {
        xs[nn * 64 + o0 + u]       = v0r[u];
        xs[(nn + 1) * 64 + o0 + u] = v1r[u];
    }
    __syncthreads();
    // q/k = t * QK_SCALE in [n][c] layout (exp2-ready logits)
    __half* thb = g_th + ((size_t)head * NSEQ + n0) * DD;
    for (int idx = tid; idx < 2048; idx += 256) {
        int n = idx >> 5, c2 = (idx & 31) * 2;
        __half2 hh;
        hh.x = __float2half_rn(xs[n * 64 + c2] * QK_SCALE);
        hh.y = __float2half_rn(xs[n * 64 + c2 + 1] * QK_SCALE);
        *(__half2*)(thb + n * 64 + c2) = hh;
    }
}

// ---------------------------------------------------------------------------
// Kernel B: mma.sync fp16 flash attention, cp.async double-buffered K/V.
// grid (16 m-blocks, 32 heads), block 128 (4 warps x 32 query rows).
// S (in log2 units) via single fp16 QK^T; P = min(2^(S - EXP_SHIFT), 2^15);
// clamp applied to BOTH lsum and P so normalization self-cancels on hot rows.
// O accumulated unnormalized in fp32; one normalization at the end.
// Epilogue: smem-staged coalesced writes + fused GroupNorm partial sums.
// smem: Q 16KB | 2 stages x (K 8KB + V 8KB); epilogue ot overlaps stages.
// ---------------------------------------------------------------------------
#define OT_STRIDE 132
#define ATTN_SMEM (16384 + 64 * OT_STRIDE * 4)   // 50176 (>= 16384+32768 stages)

__device__ __forceinline__ void issue_tile(uint32_t bK, uint32_t bV,
                                           const __half* thB, const __half* vB,
                                           int n0, int tid) {
#pragma unroll
    for (int it = 0; it < 4; it++) {
        int idx = tid + it * 128;
        int r = idx >> 3, ch = idx & 7;
        uint32_t d = (uint32_t)((r * 8 + (ch ^ (r & 7))) * 16);
        cpa16(bK + d, thB + (size_t)n0 * 64 + idx * 8);
    }
#pragma unroll
    for (int it = 0; it < 4; it++) {
        int idx = tid + it * 128;
        int c = idx >> 3, ch = idx & 7;
        uint32_t d = (uint32_t)((c * 8 + (ch ^ (c & 7))) * 16);
        cpa16(bV + d, vB + (size_t)c * NSEQ + n0 + ch * 8);
    }
}

__global__ __launch_bounds__(128, 2)
void attn_kernel(const float* __restrict__ points, float* __restrict__ out) {
    extern __shared__ __align__(128) uint4 dynsm[];
    uint4* sQ = dynsm;                        // [BM*8] 16 KB
    const uint32_t bQ  = smem_u32(sQ);
    const uint32_t bS0 = bQ + 16384;          // stage 0: K @ +0, V @ +8192
    const uint32_t bS1 = bQ + 32768;          // stage 1

    const int tid  = threadIdx.x;
    const int wid  = tid >> 5;
    const int lane = tid & 31;
    const int grp  = lane >> 2;
    const int tq   = lane & 3;
    const int head = blockIdx.y;
    const int b    = head >> 3;
    const int hg   = head & 7;
    const int m0   = blockIdx.x * BM;
    const int wrow = wid * 32;

    const __half* thB = g_th + (size_t)head * NSEQ * DD;
    const __half* vB  = g_v  + (size_t)head * DD * NSEQ;

    // ---- Q tile load (plain, once), swizzle chunk' = chunk ^ (row&7) ----
    {
        const uint4* s1 = (const uint4*)(thB + (size_t)m0 * DD);
        for (int idx = tid; idx < BM * 8; idx += 128) {
            int r = idx >> 3, ch = idx & 7;
            sQ[r * 8 + (ch ^ (r & 7))] = s1[idx];
        }
    }
    // ---- prologue: stage 0 in flight ----
    issue_tile(bS0, bS0 + 8192, thB, vB, 0, tid);
    CP_COMMIT();
    __syncthreads();

    // ---- persistent Q fragments: [mtile][kstep][4] ----
    uint32_t qf[2][4][4];
#pragma unroll
    for (int mt = 0; mt < 2; mt++)
#pragma unroll
        for (int k = 0; k < 4; k++) {
            int row = wrow + mt * 16 + ((lane >> 3) & 1) * 8 + (lane & 7);
            int ch  = 2 * k + (lane >> 4);
            uint32_t addr = bQ + (uint32_t)((row * 8 + (ch ^ (row & 7))) * 16);
            ldsm4(qf[mt][k][0], qf[mt][k][1], qf[mt][k][2], qf[mt][k][3], addr);
        }

    float O[2][8][4];
    float lsum[2][2];
#pragma unroll
    for (int mt = 0; mt < 2; mt++) {
        lsum[mt][0] = 0.f; lsum[mt][1] = 0.f;
#pragma unroll
        for (int ct = 0; ct < 8; ct++)
#pragma unroll
            for (int r = 0; r < 4; r++) O[mt][ct][r] = 0.f;
    }

    const int brow_off = ((lane >> 4) & 1) * 8 + (lane & 7);
    const int bch_off  = (lane >> 3) & 1;

    for (int kb = 0; kb < NT; kb++) {
        // issue next tile into the other stage, then wait for current
        if (kb + 1 < NT) {
            uint32_t nb = ((kb + 1) & 1) ? bS1 : bS0;
            issue_tile(nb, nb + 8192, thB, vB, (kb + 1) * BN, tid);
            CP_COMMIT();
            CP_WAIT(1);
        } else {
            CP_WAIT(0);
        }
        __syncthreads();
        const uint32_t bK = (kb & 1) ? bS1 : bS0;
        const uint32_t bV = bK + 8192;

        // ---- GEMM1: S (log2-units logits) ----
        float S[2][8][4];
#pragma unroll
        for (int mt = 0; mt < 2; mt++)
#pragma unroll
            for (int nt = 0; nt < 8; nt++)
#pragma unroll
                for (int r = 0; r < 4; r++) S[mt][nt][r] = 0.f;

#pragma unroll
        for (int k = 0; k < 4; k++) {
            uint32_t bh[8][2];
#pragma unroll
            for (int nt2 = 0; nt2 < 4; nt2++) {
                int row = nt2 * 16 + brow_off;
                int ch  = 2 * k + bch_off;
                uint32_t addr = bK + (uint32_t)((row * 8 + (ch ^ (row & 7))) * 16);
                ldsm4(bh[2 * nt2][0], bh[2 * nt2][1], bh[2 * nt2 + 1][0],
                      bh[2 * nt2 + 1][1], addr);
            }
#pragma unroll
            for (int mt = 0; mt < 2; mt++)
#pragma unroll
                for (int nt = 0; nt < 8; nt++)
                    mma16816(S[mt][nt], qf[mt][k][0], qf[mt][k][1], qf[mt][k][2],
                             qf[mt][k][3], bh[nt][0], bh[nt][1]);
        }

        // ---- P = min(2^(S - EXP_SHIFT), P_CLAMP), fp16 A fragments ----
        uint32_t P[2][8][2];
#pragma unroll
        for (int mt = 0; mt < 2; mt++)
#pragma unroll
            for (int nt = 0; nt < 8; nt++) {
                float e0 = fminf(exp2f(S[mt][nt][0] - EXP_SHIFT), P_CLAMP);
                float e1 = fminf(exp2f(S[mt][nt][1] - EXP_SHIFT), P_CLAMP);
                float e2 = fminf(exp2f(S[mt][nt][2] - EXP_SHIFT), P_CLAMP);
                float e3 = fminf(exp2f(S[mt][nt][3] - EXP_SHIFT), P_CLAMP);
                lsum[mt][0] += e0 + e1;
                lsum[mt][1] += e2 + e3;
                P[mt][nt][0] = pack_h2(e0, e1);
                P[mt][nt][1] = pack_h2(e2, e3);
            }

        // ---- GEMM2: O += P * V ----
#pragma unroll
        for (int kn = 0; kn < 4; kn++) {
            uint32_t bv[8][2];
#pragma unroll
            for (int ct2 = 0; ct2 < 4; ct2++) {
                int row = ct2 * 16 + brow_off;
                int ch  = 2 * kn + bch_off;
                uint32_t addr = bV + (uint32_t)((row * 8 + (ch ^ (row & 7))) * 16);
                ldsm4(bv[2 * ct2][0], bv[2 * ct2][1], bv[2 * ct2 + 1][0],
                      bv[2 * ct2 + 1][1], addr);
            }
#pragma unroll
            for (int mt = 0; mt < 2; mt++)
#pragma unroll
                for (int ct = 0; ct < 8; ct++)
                    mma16816(O[mt][ct], P[mt][2 * kn][0], P[mt][2 * kn][1],
                             P[mt][2 * kn + 1][0], P[mt][2 * kn + 1][1],
                             bv[ct][0], bv[ct][1]);
        }
        __syncthreads();   // protect stage buffer reuse
    }

    // ---- epilogue ----
#pragma unroll
    for (int mt = 0; mt < 2; mt++)
#pragma unroll
        for (int h = 0; h < 2; h++) {
            float v = lsum[mt][h];
            v += __shfl_xor_sync(0xffffffffu, v, 1);
            v += __shfl_xor_sync(0xffffffffu, v, 2);
            lsum[mt][h] = v;
        }

    // stage normalized O into smem [64 c][OT_STRIDE] (overlaps dead stages)
    float* ot = (float*)((char*)dynsm + 16384);
#pragma unroll
    for (int mt = 0; mt < 2; mt++) {
        const int row_l = wrow + mt * 16 + grp;
        const float inv0 = 1.f / lsum[mt][0];
        const float inv1 = 1.f / lsum[mt][1];
#pragma unroll
        for (int ct = 0; ct < 8; ct++) {
            int c = ct * 8 + 2 * tq;
            ot[c * OT_STRIDE + row_l]           = O[mt][ct][0] * inv0;
            ot[(c + 1) * OT_STRIDE + row_l]     = O[mt][ct][1] * inv0;
            ot[c * OT_STRIDE + row_l + 8]       = O[mt][ct][2] * inv1;
            ot[(c + 1) * OT_STRIDE + row_l + 8] = O[mt][ct][3] * inv1;
        }
    }
    __syncthreads();

    // coalesced residual + writes; fused GN partial sums (group j == c>>3)
    float sj[8], qj[8];
#pragma unroll
    for (int j = 0; j < 8; j++) { sj[j] = 0.f; qj[j] = 0.f; }
#pragma unroll
    for (int c = 0; c < 64; c++) {
        size_t oi = ((size_t)(b * CC + c * GG + hg)) * NSEQ + m0 + tid;
        float v = ot[c * OT_STRIDE + tid] + points[oi];
        out[oi] = v;
        sj[c >> 3] += v;
        qj[c >> 3] += v * v;
    }
#pragma unroll
    for (int j = 0; j < 8; j++)
#pragma unroll
        for (int off = 16; off; off >>= 1) {
            sj[j] += __shfl_xor_sync(0xffffffffu, sj[j], off);
            qj[j] += __shfl_xor_sync(0xffffffffu, qj[j], off);
        }
    float* redsm = (float*)dynsm;   // Q area dead
    if (lane == 0) {
#pragma unroll
        for (int j = 0; j < 8; j++) {
            redsm[wid * 16 + j]     = sj[j];
            redsm[wid * 16 + 8 + j] = qj[j];
        }
    }
    __syncthreads();
    if (tid < 16) {
        float a = redsm[tid] + redsm[16 + tid] + redsm[32 + tid] + redsm[48 + tid];
        int j = tid & 7;
        atomicAdd(&g_stats[(b * 8 + j) * 2 + (tid >> 3)], a);
    }
}

// ---------------------------------------------------------------------------
// Kernel C: GroupNorm normalize from fused partials. grid 4096, block 256.
// ---------------------------------------------------------------------------
__global__ __launch_bounds__(256)
void gn_norm(float* __restrict__ out,
             const float* __restrict__ gw, const float* __restrict__ gb) {
    const int TOT4 = BB * CC * NSEQ / 4;
    int i4 = blockIdx.x * blockDim.x + threadIdx.x;
    if (i4 >= TOT4) return;
    int row = i4 >> 9;            // NSEQ/4 = 512 float4 per channel-row
    int cp  = row & 511;
    int b   = row >> 9;
    int bj  = (b << 3) | (cp >> 6);
    const float invN = 1.f / (64.f * NSEQ);
    float mean = g_stats[bj * 2] * invN;
    float var  = fmaxf(g_stats[bj * 2 + 1] * invN - mean * mean, 0.f);
    float rstd = rsqrtf(var + 1e-5f);
    float ws = gw[cp] * rstd;
    float sh = gb[cp] - mean * ws;
    float4 v = ((float4*)out)[i4];
    v.x = v.x * ws + sh;
    v.y = v.y * ws + sh;
    v.z = v.z * ws + sh;
    v.w = v.w * ws + sh;
    ((float4*)out)[i4] = v;
}

// ---------------------------------------------------------------------------
extern "C" void kernel_launch(void* const* d_in, const int* in_sizes, int n_in,
                              void* d_out, int out_size) {
    const float* points = (const float*)d_in[0];
    const float* conv_w = (const float*)d_in[1];
    const float* conv_b = (const float*)d_in[2];
    const float* gn_w   = (const float*)d_in[3];
    const float* gn_b   = (const float*)d_in[4];
    float* out = (float*)d_out;

    cudaFuncSetAttribute(attn_kernel,
                         cudaFuncAttributeMaxDynamicSharedMemorySize, ATTN_SMEM);

    conv_kernel<<<dim3(HEADS, NSEQ / 64), 256>>>(points, conv_w, conv_b);
    attn_kernel<<<dim3(NSEQ / BM, HEADS), 128, ATTN_SMEM>>>(points, out);
    gn_norm<<<(BB * CC * NSEQ / 4 + 255) / 256, 256>>>(out, gn_w, gn_b);
}

// round 8
// speedup vs baseline: 8.1964x; 1.1279x over previous
#include <cuda_runtime.h>
#include <cuda_fp16.h>
#include <math.h>
#include <stdint.h>

#define BB    4
#define CC    512
#define NSEQ  2048
#define GG    8
#define DD    64
#define HEADS 32
#define BM    128
#define BN    64
#define NT    (NSEQ / BN)

// q/k = t * sqrt(0.125 * log2(e)), fp16, key-major [head][n][c]
__device__ __align__(16) __half g_th[(size_t)HEADS * NSEQ * DD];
// v = elu(t), fp16, channel-major [head][c][n]
__device__ __align__(16) __half g_v[(size_t)HEADS * DD * NSEQ];
// fused GN partials: per (b,j): {sum, sumsq}
__device__ float g_stats[BB * GG * 2];

#define QK_SCALE 0.4246609001440095f     // sqrt(0.125 * log2e)
#define EXP_SHIFT 11.541560327111707f    // 8 * log2e
#define P_CLAMP 32768.0f                 // keep P finite in fp16 (hot-row guard)

// ============================ PTX helpers ==================================
__device__ __forceinline__ uint32_t smem_u32(const void* p) {
    uint32_t a;
    asm("{ .reg .u64 t; cvta.to.shared.u64 t, %1; cvt.u32.u64 %0, t; }" : "=r"(a) : "l"(p));
    return a;
}
__device__ __forceinline__ void ldsm4(uint32_t& r0, uint32_t& r1, uint32_t& r2,
                                      uint32_t& r3, uint32_t addr) {
    asm volatile("ldmatrix.sync.aligned.m8n8.x4.shared.b16 {%0,%1,%2,%3}, [%4];"
                 : "=r"(r0), "=r"(r1), "=r"(r2), "=r"(r3) : "r"(addr));
}
__device__ __forceinline__ void mma16816(float* c, uint32_t a0, uint32_t a1,
                                         uint32_t a2, uint32_t a3,
                                         uint32_t b0, uint32_t b1) {
    asm volatile("mma.sync.aligned.m16n8k16.row.col.f32.f16.f16.f32 "
                 "{%0,%1,%2,%3}, {%4,%5,%6,%7}, {%8,%9}, {%0,%1,%2,%3};"
                 : "+f"(c[0]), "+f"(c[1]), "+f"(c[2]), "+f"(c[3])
                 : "r"(a0), "r"(a1), "r"(a2), "r"(a3), "r"(b0), "r"(b1));
}
__device__ __forceinline__ uint32_t pack_h2(float lo, float hi) {
    uint32_t r;
    asm("cvt.rn.f16x2.f32 %0, %1, %2;" : "=r"(r) : "f"(hi), "f"(lo));
    return r;
}
__device__ __forceinline__ void cpa16(uint32_t dst, const void* src) {
    asm volatile("cp.async.cg.shared.global [%0], [%1], 16;" :: "r"(dst), "l"(src));
}
#define CP_COMMIT() asm volatile("cp.async.commit_group;" ::: "memory")
#define CP_WAIT(n)  asm volatile("cp.async.wait_group %0;" :: "n"(n) : "memory")

// ---------------------------------------------------------------------------
// Kernel A: grouped 1x1 conv -> fp16 scaled t ([n][c]) + fp16 elu(t) ([c][n])
// grid (32 heads, 32 n-blocks), block 256.
// Register-direct stores: no smem transpose (was a 32-way-bank-conflict hot
// spot), no extra barriers, single pass.
// ---------------------------------------------------------------------------
__global__ __launch_bounds__(256)
void conv_kernel(const float* __restrict__ points,
                 const float* __restrict__ cw,
                 const float* __restrict__ cb) {
    __shared__ float WsT[64 * 64];   // [i][o]
    __shared__ float xs[64 * 64];    // [i][n]
    const int head = blockIdx.x;
    const int g    = head & 7;
    const int n0   = blockIdx.y * 64;
    const int tid  = threadIdx.x;

    if (head == 0 && blockIdx.y == 0 && tid < BB * GG * 2)
        g_stats[tid] = 0.f;          // reset fused-GN accumulators each launch

    for (int idx = tid; idx < 4096; idx += 256) {
        int o = idx >> 6, i = idx & 63;
        WsT[i * 64 + o] = cw[(g * 64 + o) * 64 + i];
    }
    const float* xb = points + (size_t)head * DD * NSEQ + n0;
    for (int idx = tid; idx < 4096; idx += 256) {
        int i = idx >> 6, n = idx & 63;
        xs[i * 64 + n] = xb[(size_t)i * NSEQ + n];
    }
    __syncthreads();

    const int o0 = (tid >> 5) * 8;   // warp -> 8 output channels (broadcast W)
    const int nn = (tid & 31) * 2;   // lane -> 2 n-columns
    float acc0[8], acc1[8];
#pragma unroll
    for (int u = 0; u < 8; u++) { acc0[u] = 0.f; acc1[u] = 0.f; }
    for (int i = 0; i < 64; i++) {
        float x0 = xs[i * 64 + nn];
        float x1 = xs[i * 64 + nn + 1];
        float4 wa = *(const float4*)&WsT[i * 64 + o0];
        float4 wb = *(const float4*)&WsT[i * 64 + o0 + 4];
        acc0[0] += wa.x * x0; acc1[0] += wa.x * x1;
        acc0[1] += wa.y * x0; acc1[1] += wa.y * x1;
        acc0[2] += wa.z * x0; acc1[2] += wa.z * x1;
        acc0[3] += wa.w * x0; acc1[3] += wa.w * x1;
        acc0[4] += wb.x * x0; acc1[4] += wb.x * x1;
        acc0[5] += wb.y * x0; acc1[5] += wb.y * x1;
        acc0[6] += wb.z * x0; acc1[6] += wb.z * x1;
        acc0[7] += wb.w * x0; acc1[7] += wb.w * x1;
    }
    float v0r[8], v1r[8];
    const float4 ba = *(const float4*)&cb[g * 64 + o0];
    const float4 bb = *(const float4*)&cb[g * 64 + o0 + 4];
    const float bias[8] = {ba.x, ba.y, ba.z, ba.w, bb.x, bb.y, bb.z, bb.w};
#pragma unroll
    for (int u = 0; u < 8; u++) {
        v0r[u] = acc0[u] + bias[u];
        v1r[u] = acc1[u] + bias[u];
    }

    // V = elu(t), [c][n]-major (coalesced in n)
    __half* vb = g_v + (size_t)head * DD * NSEQ + n0 + nn;
#pragma unroll
    for (int u = 0; u < 8; u++) {
        float e0 = (v0r[u] > 0.f) ? v0r[u] : (__expf(v0r[u]) - 1.f);
        float e1 = (v1r[u] > 0.f) ? v1r[u] : (__expf(v1r[u]) - 1.f);
        __half2 p;
        p.x = __float2half_rn(e0);
        p.y = __float2half_rn(e1);
        *(__half2*)(vb + (size_t)(o0 + u) * NSEQ) = p;
    }

    // q/k = t * QK_SCALE, [n][c]-major, 16B register-direct stores
    {
        union { uint4 u4; __half h[8]; } r0, r1;
#pragma unroll
        for (int u = 0; u < 8; u++) {
            r0.h[u] = __float2half_rn(v0r[u] * QK_SCALE);
            r1.h[u] = __float2half_rn(v1r[u] * QK_SCALE);
        }
        __half* thb = g_th + ((size_t)head * NSEQ + n0) * DD + o0;
        *(uint4*)(thb + (size_t)nn * DD)       = r0.u4;
        *(uint4*)(thb + (size_t)(nn + 1) * DD) = r1.u4;
    }
}

// ---------------------------------------------------------------------------
// Kernel B: mma.sync fp16 flash attention, cp.async double-buffered K/V.
// grid (16 m-blocks, 32 heads), block 128 (4 warps x 32 query rows).
// S (in log2 units) via single fp16 QK^T; P = min(2^(S - EXP_SHIFT), 2^15);
// clamp applied to BOTH lsum and P so normalization self-cancels on hot rows.
// O accumulated unnormalized in fp32; one normalization at the end.
// Epilogue: smem-staged coalesced writes + fused GroupNorm partial sums.
// smem: Q 16KB | 2 stages x (K 8KB + V 8KB); epilogue ot overlaps stages.
// ---------------------------------------------------------------------------
#define OT_STRIDE 132
#define ATTN_SMEM (16384 + 64 * OT_STRIDE * 4)   // 50176 (>= 16384+32768 stages)

__device__ __forceinline__ void issue_tile(uint32_t bK, uint32_t bV,
                                           const __half* thB, const __half* vB,
                                           int n0, int tid) {
#pragma unroll
    for (int it = 0; it < 4; it++) {
        int idx = tid + it * 128;
        int r = idx >> 3, ch = idx & 7;
        uint32_t d = (uint32_t)((r * 8 + (ch ^ (r & 7))) * 16);
        cpa16(bK + d, thB + (size_t)n0 * 64 + idx * 8);
    }
#pragma unroll
    for (int it = 0; it < 4; it++) {
        int idx = tid + it * 128;
        int c = idx >> 3, ch = idx & 7;
        uint32_t d = (uint32_t)((c * 8 + (ch ^ (c & 7))) * 16);
        cpa16(bV + d, vB + (size_t)c * NSEQ + n0 + ch * 8);
    }
}

__global__ __launch_bounds__(128, 2)
void attn_kernel(const float* __restrict__ points, float* __restrict__ out) {
    extern __shared__ __align__(128) uint4 dynsm[];
    uint4* sQ = dynsm;                        // [BM*8] 16 KB
    const uint32_t bQ  = smem_u32(sQ);
    const uint32_t bS0 = bQ + 16384;          // stage 0: K @ +0, V @ +8192
    const uint32_t bS1 = bQ + 32768;          // stage 1

    const int tid  = threadIdx.x;
    const int wid  = tid >> 5;
    const int lane = tid & 31;
    const int grp  = lane >> 2;
    const int tq   = lane & 3;
    const int head = blockIdx.y;
    const int b    = head >> 3;
    const int hg   = head & 7;
    const int m0   = blockIdx.x * BM;
    const int wrow = wid * 32;

    const __half* thB = g_th + (size_t)head * NSEQ * DD;
    const __half* vB  = g_v  + (size_t)head * DD * NSEQ;

    // ---- Q tile load (plain, once), swizzle chunk' = chunk ^ (row&7) ----
    {
        const uint4* s1 = (const uint4*)(thB + (size_t)m0 * DD);
        for (int idx = tid; idx < BM * 8; idx += 128) {
            int r = idx >> 3, ch = idx & 7;
            sQ[r * 8 + (ch ^ (r & 7))] = s1[idx];
        }
    }
    // ---- prologue: stage 0 in flight ----
    issue_tile(bS0, bS0 + 8192, thB, vB, 0, tid);
    CP_COMMIT();
    __syncthreads();

    // ---- persistent Q fragments: [mtile][kstep][4] ----
    uint32_t qf[2][4][4];
#pragma unroll
    for (int mt = 0; mt < 2; mt++)
#pragma unroll
        for (int k = 0; k < 4; k++) {
            int row = wrow + mt * 16 + ((lane >> 3) & 1) * 8 + (lane & 7);
            int ch  = 2 * k + (lane >> 4);
            uint32_t addr = bQ + (uint32_t)((row * 8 + (ch ^ (row & 7))) * 16);
            ldsm4(qf[mt][k][0], qf[mt][k][1], qf[mt][k][2], qf[mt][k][3], addr);
        }

    float O[2][8][4];
    float lsum[2][2];
#pragma unroll
    for (int mt = 0; mt < 2; mt++) {
        lsum[mt][0] = 0.f; lsum[mt][1] = 0.f;
#pragma unroll
        for (int ct = 0; ct < 8; ct++)
#pragma unroll
            for (int r = 0; r < 4; r++) O[mt][ct][r] = 0.f;
    }

    const int brow_off = ((lane >> 4) & 1) * 8 + (lane & 7);
    const int bch_off  = (lane >> 3) & 1;

    for (int kb = 0; kb < NT; kb++) {
        // issue next tile into the other stage, then wait for current
        if (kb + 1 < NT) {
            uint32_t nb = ((kb + 1) & 1) ? bS1 : bS0;
            issue_tile(nb, nb + 8192, thB, vB, (kb + 1) * BN, tid);
            CP_COMMIT();
            CP_WAIT(1);
        } else {
            CP_WAIT(0);
        }
        __syncthreads();
        const uint32_t bK = (kb & 1) ? bS1 : bS0;
        const uint32_t bV = bK + 8192;

        // ---- GEMM1: S (log2-units logits) ----
        float S[2][8][4];
#pragma unroll
        for (int mt = 0; mt < 2; mt++)
#pragma unroll
            for (int nt = 0; nt < 8; nt++)
#pragma unroll
                for (int r = 0; r < 4; r++) S[mt][nt][r] = 0.f;

#pragma unroll
        for (int k = 0; k < 4; k++) {
            uint32_t bh[8][2];
#pragma unroll
            for (int nt2 = 0; nt2 < 4; nt2++) {
                int row = nt2 * 16 + brow_off;
                int ch  = 2 * k + bch_off;
                uint32_t addr = bK + (uint32_t)((row * 8 + (ch ^ (row & 7))) * 16);
                ldsm4(bh[2 * nt2][0], bh[2 * nt2][1], bh[2 * nt2 + 1][0],
                      bh[2 * nt2 + 1][1], addr);
            }
#pragma unroll
            for (int mt = 0; mt < 2; mt++)
#pragma unroll
                for (int nt = 0; nt < 8; nt++)
                    mma16816(S[mt][nt], qf[mt][k][0], qf[mt][k][1], qf[mt][k][2],
                             qf[mt][k][3], bh[nt][0], bh[nt][1]);
        }

        // ---- P = min(2^(S - EXP_SHIFT), P_CLAMP), fp16 A fragments ----
        uint32_t P[2][8][2];
#pragma unroll
        for (int mt = 0; mt < 2; mt++)
#pragma unroll
            for (int nt = 0; nt < 8; nt++) {
                float e0 = fminf(exp2f(S[mt][nt][0] - EXP_SHIFT), P_CLAMP);
                float e1 = fminf(exp2f(S[mt][nt][1] - EXP_SHIFT), P_CLAMP);
                float e2 = fminf(exp2f(S[mt][nt][2] - EXP_SHIFT), P_CLAMP);
                float e3 = fminf(exp2f(S[mt][nt][3] - EXP_SHIFT), P_CLAMP);
                lsum[mt][0] += e0 + e1;
                lsum[mt][1] += e2 + e3;
                P[mt][nt][0] = pack_h2(e0, e1);
                P[mt][nt][1] = pack_h2(e2, e3);
            }

        // ---- GEMM2: O += P * V ----
#pragma unroll
        for (int kn = 0; kn < 4; kn++) {
            uint32_t bv[8][2];
#pragma unroll
            for (int ct2 = 0; ct2 < 4; ct2++) {
                int row = ct2 * 16 + brow_off;
                int ch  = 2 * kn + bch_off;
                uint32_t addr = bV + (uint32_t)((row * 8 + (ch ^ (row & 7))) * 16);
                ldsm4(bv[2 * ct2][0], bv[2 * ct2][1], bv[2 * ct2 + 1][0],
                      bv[2 * ct2 + 1][1], addr);
            }
#pragma unroll
            for (int mt = 0; mt < 2; mt++)
#pragma unroll
                for (int ct = 0; ct < 8; ct++)
                    mma16816(O[mt][ct], P[mt][2 * kn][0], P[mt][2 * kn][1],
                             P[mt][2 * kn + 1][0], P[mt][2 * kn + 1][1],
                             bv[ct][0], bv[ct][1]);
        }
        __syncthreads();   // protect stage buffer reuse
    }

    // ---- epilogue ----
#pragma unroll
    for (int mt = 0; mt < 2; mt++)
#pragma unroll
        for (int h = 0; h < 2; h++) {
            float v = lsum[mt][h];
            v += __shfl_xor_sync(0xffffffffu, v, 1);
            v += __shfl_xor_sync(0xffffffffu, v, 2);
            lsum[mt][h] = v;
        }

    // stage normalized O into smem [64 c][OT_STRIDE] (overlaps dead stages)
    float* ot = (float*)((char*)dynsm + 16384);
#pragma unroll
    for (int mt = 0; mt < 2; mt++) {
        const int row_l = wrow + mt * 16 + grp;
        const float inv0 = 1.f / lsum[mt][0];
        const float inv1 = 1.f / lsum[mt][1];
#pragma unroll
        for (int ct = 0; ct < 8; ct++) {
            int c = ct * 8 + 2 * tq;
            ot[c * OT_STRIDE + row_l]           = O[mt][ct][0] * inv0;
            ot[(c + 1) * OT_STRIDE + row_l]     = O[mt][ct][1] * inv0;
            ot[c * OT_STRIDE + row_l + 8]       = O[mt][ct][2] * inv1;
            ot[(c + 1) * OT_STRIDE + row_l + 8] = O[mt][ct][3] * inv1;
        }
    }
    __syncthreads();

    // coalesced residual + writes; fused GN partial sums (group j == c>>3)
    float sj[8], qj[8];
#pragma unroll
    for (int j = 0; j < 8; j++) { sj[j] = 0.f; qj[j] = 0.f; }
#pragma unroll
    for (int c = 0; c < 64; c++) {
        size_t oi = ((size_t)(b * CC + c * GG + hg)) * NSEQ + m0 + tid;
        float v = ot[c * OT_STRIDE + tid] + points[oi];
        out[oi] = v;
        sj[c >> 3] += v;
        qj[c >> 3] += v * v;
    }
#pragma unroll
    for (int j = 0; j < 8; j++)
#pragma unroll
        for (int off = 16; off; off >>= 1) {
            sj[j] += __shfl_xor_sync(0xffffffffu, sj[j], off);
            qj[j] += __shfl_xor_sync(0xffffffffu, qj[j], off);
        }
    float* redsm = (float*)dynsm;   // Q area dead
    if (lane == 0) {
#pragma unroll
        for (int j = 0; j < 8; j++) {
            redsm[wid * 16 + j]     = sj[j];
            redsm[wid * 16 + 8 + j] = qj[j];
        }
    }
    __syncthreads();
    if (tid < 16) {
        float a = redsm[tid] + redsm[16 + tid] + redsm[32 + tid] + redsm[48 + tid];
        int j = tid & 7;
        atomicAdd(&g_stats[(b * 8 + j) * 2 + (tid >> 3)], a);
    }
}

// ---------------------------------------------------------------------------
// Kernel C: GroupNorm normalize from fused partials. grid 4096, block 256.
// ---------------------------------------------------------------------------
__global__ __launch_bounds__(256)
void gn_norm(float* __restrict__ out,
             const float* __restrict__ gw, const float* __restrict__ gb) {
    const int TOT4 = BB * CC * NSEQ / 4;
    int i4 = blockIdx.x * blockDim.x + threadIdx.x;
    if (i4 >= TOT4) return;
    int row = i4 >> 9;            // NSEQ/4 = 512 float4 per channel-row
    int cp  = row & 511;
    int b   = row >> 9;
    int bj  = (b << 3) | (cp >> 6);
    const float invN = 1.f / (64.f * NSEQ);
    float mean = g_stats[bj * 2] * invN;
    float var  = fmaxf(g_stats[bj * 2 + 1] * invN - mean * mean, 0.f);
    float rstd = rsqrtf(var + 1e-5f);
    float ws = gw[cp] * rstd;
    float sh = gb[cp] - mean * ws;
    float4 v = ((float4*)out)[i4];
    v.x = v.x * ws + sh;
    v.y = v.y * ws + sh;
    v.z = v.z * ws + sh;
    v.w = v.w * ws + sh;
    ((float4*)out)[i4] = v;
}

// ---------------------------------------------------------------------------
extern "C" void kernel_launch(void* const* d_in, const int* in_sizes, int n_in,
                              void* d_out, int out_size) {
    const float* points = (const float*)d_in[0];
    const float* conv_w = (const float*)d_in[1];
    const float* conv_b = (const float*)d_in[2];
    const float* gn_w   = (const float*)d_in[3];
    const float* gn_b   = (const float*)d_in[4];
    float* out = (float*)d_out;

    cudaFuncSetAttribute(attn_kernel,
                         cudaFuncAttributeMaxDynamicSharedMemorySize, ATTN_SMEM);

    conv_kernel<<<dim3(HEADS, NSEQ / 64), 256>>>(points, conv_w, conv_b);
    attn_kernel<<<dim3(NSEQ / BM, HEADS), 128, ATTN_SMEM>>>(points, out);
    gn_norm<<<(BB * CC * NSEQ / 4 + 255) / 256, 256>>>(out, gn_w, gn_b);
}